// round 3
// baseline (speedup 1.0000x reference)
#include <cuda_runtime.h>
#include <cuda_bf16.h>
#include <math.h>

// ---------------- problem constants ----------------
#define N_LANG   64
#define N_EX     4
#define N_IMG    (N_LANG * N_EX)        // 256
#define M_REG    49
#define L_TOK    32
#define HDIM     512
#define MP1      (M_REG + 1)            // 50
#define LP1      (L_TOK + 1)            // 33
#define NB       (N_IMG * N_LANG)       // 16384 batch items
#define XROWS    (N_IMG * M_REG)        // 12544
#define YROWS    (N_LANG * L_TOK)       // 2048
#define REG      0.1f
#define INVREG   10.0f
#define TEMP     0.1f
#define ITERS    10
#define NEGV     (-1.0e7f)              // NEG / REG

// scratch (static device allocations are the sanctioned workaround)
__device__ float g_xn[(size_t)XROWS * HDIM];      // 25.7 MB
__device__ float g_yn[(size_t)YROWS * HDIM];      //  4.2 MB
__device__ float g_scores[(size_t)XROWS * YROWS]; // 102.8 MB  C[row, col]
__device__ float g_ot[NB];                        // 64 KB
__device__ unsigned char g_mask[YROWS];           // decoded y_mask (2048 bytes)

// ---------------- 0) decode y_mask regardless of storage dtype ----------------
// The reference produces a bool array; the harness may pass it as uint8, int32,
// or float32. Detection: read the first 512 aligned int32 words (2048 bytes,
// in-bounds under every hypothesis). If ALL are in {0, 1, 0x3f800000} the data
// is word-encoded (int32/float32); decode word != 0. Otherwise byte-encoded.
// (A byte-mask of suffix-of-ones rows can never make an aligned word equal 1,
// so detection is unambiguous; the all-zero case decodes identically.)
__global__ void decode_mask_kernel(const void* __restrict__ p) {
    __shared__ int bad;
    if (threadIdx.x == 0) bad = 0;
    __syncthreads();
    const int* ip = (const int*)p;
    for (int k = threadIdx.x; k < 512; k += blockDim.x) {
        int w = ip[k];
        if (w != 0 && w != 1 && w != 0x3f800000) atomicOr(&bad, 1);
    }
    __syncthreads();
    if (bad) {  // byte-encoded mask
        const unsigned char* bp = (const unsigned char*)p;
        for (int k = threadIdx.x; k < YROWS; k += blockDim.x)
            g_mask[k] = bp[k] ? 1 : 0;
    } else {    // 4-byte-encoded mask (int32 0/1 or float32 0.0/1.0)
        for (int k = threadIdx.x; k < YROWS; k += blockDim.x)
            g_mask[k] = ip[k] ? 1 : 0;
    }
}

// ---------------- 1) L2 normalize rows of x and y ----------------
__global__ void norm_kernel(const float* __restrict__ x, const float* __restrict__ y) {
    int row  = (blockIdx.x * blockDim.x + threadIdx.x) >> 5;
    int lane = threadIdx.x & 31;
    if (row >= XROWS + YROWS) return;
    const float* src;
    float* dst;
    if (row < XROWS) { src = x + (size_t)row * HDIM;           dst = g_xn + (size_t)row * HDIM; }
    else             { src = y + (size_t)(row - XROWS) * HDIM; dst = g_yn + (size_t)(row - XROWS) * HDIM; }

    const float4* s4 = (const float4*)src;
    float4 v[4];
    float ss = 0.f;
#pragma unroll
    for (int q = 0; q < 4; q++) {
        v[q] = s4[lane + 32 * q];
        ss += v[q].x * v[q].x + v[q].y * v[q].y + v[q].z * v[q].z + v[q].w * v[q].w;
    }
#pragma unroll
    for (int o = 16; o; o >>= 1) ss += __shfl_xor_sync(0xffffffffu, ss, o);
    float inv = 1.0f / fmaxf(sqrtf(ss), 1e-12f);
    float4* d4 = (float4*)dst;
#pragma unroll
    for (int q = 0; q < 4; q++) {
        float4 w = v[q];
        w.x *= inv; w.y *= inv; w.z *= inv; w.w *= inv;
        d4[lane + 32 * q] = w;
    }
}

// ---------------- 2) scores GEMM: C[12544,2048] = Xn (12544x512) * Yn^T ----
// 128x128x8 tile, 256 threads, 8x8 micro-tile, packed fma.rn.f32x2 (Blackwell).
// Thread (ty,tx): rows m0+ty*8..+7, cols n0 + g*32 + tx*2 (+0,1) for g=0..3.
#define BM 128
#define BN 128
#define BK 8
#define SSTRIDE 132   // smem row stride (floats): kills both store & load conflicts

__device__ __forceinline__ unsigned long long pack_dup(float x) {
    unsigned long long r;
    asm("mov.b64 %0, {%1, %1};" : "=l"(r) : "f"(x));
    return r;
}
__device__ __forceinline__ void ffma2(unsigned long long& d, unsigned long long a,
                                      unsigned long long b) {
    asm("fma.rn.f32x2 %0, %1, %2, %0;" : "+l"(d) : "l"(a), "l"(b));
}

__global__ __launch_bounds__(256) void gemm_kernel() {
    __shared__ float As[BK * SSTRIDE];
    __shared__ float Bs[BK * SSTRIDE];
    const int tid = threadIdx.x;
    const int m0 = blockIdx.y * BM;
    const int n0 = blockIdx.x * BN;

    const int lrow = tid >> 1;            // 0..127
    const int lk4  = (tid & 1) * 4;       // 0 or 4
    const int ty   = tid >> 4;            // 0..15 -> row group
    const int tx   = tid & 15;            // 0..15 -> col pairs

    const float* Aptr = g_xn + (size_t)(m0 + lrow) * HDIM + lk4;
    const float* Bptr = g_yn + (size_t)(n0 + lrow) * HDIM + lk4;

    unsigned long long acc[8][4];
#pragma unroll
    for (int r = 0; r < 8; r++)
#pragma unroll
        for (int g = 0; g < 4; g++) acc[r][g] = 0ULL;

    float4 af = *(const float4*)Aptr;
    float4 bf = *(const float4*)Bptr;

    const int NT = HDIM / BK;   // 64 k-tiles
    for (int kt = 0; kt < NT; kt++) {
        As[(lk4 + 0) * SSTRIDE + lrow] = af.x;
        As[(lk4 + 1) * SSTRIDE + lrow] = af.y;
        As[(lk4 + 2) * SSTRIDE + lrow] = af.z;
        As[(lk4 + 3) * SSTRIDE + lrow] = af.w;
        Bs[(lk4 + 0) * SSTRIDE + lrow] = bf.x;
        Bs[(lk4 + 1) * SSTRIDE + lrow] = bf.y;
        Bs[(lk4 + 2) * SSTRIDE + lrow] = bf.z;
        Bs[(lk4 + 3) * SSTRIDE + lrow] = bf.w;
        __syncthreads();
        if (kt + 1 < NT) {
            af = *(const float4*)(Aptr + (kt + 1) * BK);
            bf = *(const float4*)(Bptr + (kt + 1) * BK);
        }
#pragma unroll
        for (int k = 0; k < BK; k++) {
            const float* arow = &As[k * SSTRIDE + ty * 8];
            float4 a01 = *(const float4*)(arow);
            float4 a23 = *(const float4*)(arow + 4);
            const float* brow = &Bs[k * SSTRIDE];
            unsigned long long b0 = *(const unsigned long long*)(brow + tx * 2);
            unsigned long long b1 = *(const unsigned long long*)(brow + 32 + tx * 2);
            unsigned long long b2 = *(const unsigned long long*)(brow + 64 + tx * 2);
            unsigned long long b3 = *(const unsigned long long*)(brow + 96 + tx * 2);
            float av[8] = {a01.x, a01.y, a01.z, a01.w, a23.x, a23.y, a23.z, a23.w};
#pragma unroll
            for (int r = 0; r < 8; r++) {
                unsigned long long aa = pack_dup(av[r]);
                ffma2(acc[r][0], aa, b0);
                ffma2(acc[r][1], aa, b1);
                ffma2(acc[r][2], aa, b2);
                ffma2(acc[r][3], aa, b3);
            }
        }
        __syncthreads();
    }

    // epilogue: 8 rows x 4 groups of 64-bit stores (coalesced per group)
#pragma unroll
    for (int r = 0; r < 8; r++) {
        float* crow = &g_scores[(size_t)(m0 + ty * 8 + r) * YROWS + n0];
#pragma unroll
        for (int g = 0; g < 4; g++) {
            *(unsigned long long*)(crow + g * 32 + tx * 2) = acc[r][g];
        }
    }
}

// ---------------- 3) per-pair Sinkhorn (log domain, /REG-scaled) ----------------
__global__ __launch_bounds__(64) void sinkhorn_kernel(const float* __restrict__ dbim,
                                                      const float* __restrict__ dblang,
                                                      float* __restrict__ out_match) {
    __shared__ float Zr[MP1 * LP1];
    __shared__ float U[MP1];
    __shared__ float V[LP1];
    __shared__ unsigned char mc[LP1];
    __shared__ float sh_ns;
    __shared__ float wsum[2];

    const int bi = blockIdx.x;
    const int i = bi >> 6;       // image 0..255
    const int j = bi & 63;       // lang  0..63
    const int tid = threadIdx.x; // 64 threads

    if (tid < L_TOK) mc[tid] = g_mask[j * L_TOK + tid];
    if (tid == L_TOK) mc[L_TOK] = 0;
    __syncthreads();
    if (tid == 0) {
        int valid = 0;
        for (int c = 0; c < L_TOK; c++) valid += mc[c] ? 0 : 1;
        sh_ns = (float)valid;
    }

    const float a_im   = fminf(fmaxf(dbim[0],   -1.f), 1.f);
    const float a_lang = fminf(fmaxf(dblang[0], -1.f), 1.f);
    const float binc = a_im   * INVREG;  // col 32 (all rows) and corner
    const float binr = a_lang * INVREG;  // row 49, cols < 32

    const float* sbase = g_scores + (size_t)i * M_REG * YROWS + (size_t)j * L_TOK;
    for (int idx = tid; idx < MP1 * LP1; idx += 64) {
        int r = idx / LP1, c = idx - r * LP1;
        float val;
        if (c < L_TOK) {
            if (mc[c])          val = NEGV;
            else if (r < M_REG) val = sbase[(size_t)r * YROWS + c] * INVREG;
            else                val = binr;
        } else {
            val = binc;
        }
        Zr[idx] = val;
    }
    if (tid < MP1) U[tid] = 0.f;
    if (tid < LP1) V[tid] = (tid < L_TOK && mc[tid]) ? NEGV : 0.f;
    __syncthreads();

    const float ns = sh_ns;
    const float norm = -__logf((float)M_REG + ns);
    const float lmu_main = norm;
    const float lmu_bin  = __logf(ns) + norm;
    const float lnu_main = norm;
    const float lnu_bin  = __logf((float)M_REG) + norm;

    for (int it = 0; it < ITERS; it++) {
        // row pass: update U  (U_new = log_mu - LSE_c(Zr + V); old U cancels)
        if (tid < MP1) {
            const float* z = &Zr[tid * LP1];
            float mx = -INFINITY;
#pragma unroll 1
            for (int c = 0; c < LP1; c++) mx = fmaxf(mx, z[c] + V[c]);
            float s = 0.f;
#pragma unroll 1
            for (int c = 0; c < LP1; c++) s += __expf(z[c] + V[c] - mx);
            U[tid] = (tid < M_REG ? lmu_main : lmu_bin) - mx - __logf(s);
        }
        __syncthreads();
        // col pass: update V (valid columns only; masked stay at NEGV)
        if (tid < LP1 && !(tid < L_TOK && mc[tid])) {
            float mx = -INFINITY;
#pragma unroll 1
            for (int r = 0; r < MP1; r++) mx = fmaxf(mx, Zr[r * LP1 + tid] + U[r]);
            float s = 0.f;
#pragma unroll 1
            for (int r = 0; r < MP1; r++) s += __expf(Zr[r * LP1 + tid] + U[r] - mx);
            V[tid] = (tid < L_TOK ? lnu_main : lnu_bin) - mx - __logf(s);
        }
        __syncthreads();
    }

    // finalize: Zm = exp(Zr + U + V - norm); matching output + ot partial
    float part = 0.f;
    for (int idx = tid; idx < MP1 * LP1; idx += 64) {
        int r = idx / LP1, c = idx - r * LP1;
        float zr = Zr[idx];
        float zm = __expf(zr + U[r] + V[c] - norm);
        if (out_match) out_match[(size_t)bi * (MP1 * LP1) + idx] = zm;
        if (r < M_REG && c < L_TOK) part += zr * zm;   // zr = score/REG
    }
#pragma unroll
    for (int o = 16; o; o >>= 1) part += __shfl_down_sync(0xffffffffu, part, o);
    if ((tid & 31) == 0) wsum[tid >> 5] = part;
    __syncthreads();
    if (tid == 0) g_ot[bi] = (wsum[0] + wsum[1]) * (REG / TEMP);
}

// ---------------- 4) InfoNCE loss over ot_scores (256x64) ----------------
__global__ __launch_bounds__(256) void loss_kernel(float* __restrict__ out_loss) {
    __shared__ float sl[8], si[8];
    const int i = threadIdx.x;        // image index 0..255
    const int grp = i >> 2;           // lang of image i
    const float* row = g_ot + i * N_LANG;
    const float pos = row[grp];

    float mx = -INFINITY;
    for (int c = 0; c < N_LANG; c++) mx = fmaxf(mx, row[c]);
    float s = 0.f;
    for (int c = 0; c < N_LANG; c++) s += __expf(row[c] - mx);
    float t_lang = pos - (mx + __logf(s));

    float mx2 = -INFINITY;
    for (int k = 0; k < N_IMG; k++) {
        if (((k >> 2) != grp) || (k == i)) mx2 = fmaxf(mx2, g_ot[k * N_LANG + grp]);
    }
    float s2 = 0.f;
    for (int k = 0; k < N_IMG; k++) {
        if (((k >> 2) != grp) || (k == i)) s2 += __expf(g_ot[k * N_LANG + grp] - mx2);
    }
    float t_im = pos - (mx2 + __logf(s2));

#pragma unroll
    for (int o = 16; o; o >>= 1) {
        t_lang += __shfl_down_sync(0xffffffffu, t_lang, o);
        t_im   += __shfl_down_sync(0xffffffffu, t_im, o);
    }
    if ((i & 31) == 0) { sl[i >> 5] = t_lang; si[i >> 5] = t_im; }
    __syncthreads();
    if (i == 0) {
        float a = 0.f, b = 0.f;
        for (int w = 0; w < 8; w++) { a += sl[w]; b += si[w]; }
        // loss = 0.5*(-mean(t_lang)) + 0.5*(-mean(t_im))
        *out_loss = -0.5f * (a + b) / (float)N_IMG;
    }
}

// ---------------- launcher ----------------
extern "C" void kernel_launch(void* const* d_in, const int* in_sizes, int n_in,
                              void* d_out, int out_size) {
    const float* x      = (const float*)d_in[0];
    const float* y      = (const float*)d_in[1];
    const float* dbim   = (const float*)d_in[2];
    const float* dblang = (const float*)d_in[3];
    const void*  ymask  = d_in[4];

    float* outF = (float*)d_out;
    const long long MATCH = (long long)NB * MP1 * LP1;   // 27,033,600
    float* matchPtr = outF;
    float* lossPtr;
    if ((long long)out_size >= MATCH + 1) lossPtr = outF + MATCH;
    else if (out_size == 1)               { lossPtr = outF; matchPtr = nullptr; }
    else                                   lossPtr = outF;  // fallback

    decode_mask_kernel<<<1, 256>>>(ymask);
    {   // normalize
        int rows = XROWS + YROWS;
        int threads = 256;
        int blocks = (rows * 32 + threads - 1) / threads;
        norm_kernel<<<blocks, threads>>>(x, y);
    }
    {   // GEMM: 12544/128 = 98, 2048/128 = 16
        dim3 grid(YROWS / BN, XROWS / BM);
        gemm_kernel<<<grid, 256>>>();
    }
    {   // sinkhorn per (image, lang) pair
        sinkhorn_kernel<<<NB, 64>>>(dbim, dblang, matchPtr);
    }
    {   // loss
        loss_kernel<<<1, 256>>>(lossPtr);
    }
}

// round 6
// speedup vs baseline: 1.3361x; 1.3361x over previous
#include <cuda_runtime.h>
#include <cuda_bf16.h>
#include <math.h>

// ---------------- problem constants ----------------
#define N_LANG   64
#define N_EX     4
#define N_IMG    (N_LANG * N_EX)        // 256
#define M_REG    49
#define L_TOK    32
#define HDIM     512
#define MP1      (M_REG + 1)            // 50
#define LP1      (L_TOK + 1)            // 33
#define NB       (N_IMG * N_LANG)       // 16384 batch items
#define XROWS    (N_IMG * M_REG)        // 12544
#define YROWS    (N_LANG * L_TOK)       // 2048
#define REG      0.1f
#define INVREG   10.0f
#define TEMP     0.1f
#define ITERS    10
#define NEGV     (-1.0e7f)              // sentinel (exp2 -> 0)
#define LOG2E    1.4426950408889634f
#define LN2      0.6931471805599453f

// scratch (static device allocations are the sanctioned workaround)
__device__ float g_xn[(size_t)XROWS * HDIM];      // 25.7 MB
__device__ float g_yn[(size_t)YROWS * HDIM];      //  4.2 MB
__device__ float g_scores[(size_t)XROWS * YROWS]; // 102.8 MB  C[row, col]
__device__ float g_ot[NB];                        // 64 KB
__device__ unsigned char g_mask[YROWS];           // decoded y_mask (2048 bytes)

__device__ __forceinline__ float ex2f(float x) {
    float r; asm("ex2.approx.ftz.f32 %0, %1;" : "=f"(r) : "f"(x)); return r;
}

// ---------------- 0) decode y_mask regardless of storage dtype ----------------
__global__ void decode_mask_kernel(const void* __restrict__ p) {
    __shared__ int bad;
    if (threadIdx.x == 0) bad = 0;
    __syncthreads();
    const int* ip = (const int*)p;
    for (int k = threadIdx.x; k < 512; k += blockDim.x) {
        int w = ip[k];
        if (w != 0 && w != 1 && w != 0x3f800000) atomicOr(&bad, 1);
    }
    __syncthreads();
    if (bad) {  // byte-encoded mask
        const unsigned char* bp = (const unsigned char*)p;
        for (int k = threadIdx.x; k < YROWS; k += blockDim.x)
            g_mask[k] = bp[k] ? 1 : 0;
    } else {    // 4-byte-encoded mask (int32 0/1 or float32 0.0/1.0)
        for (int k = threadIdx.x; k < YROWS; k += blockDim.x)
            g_mask[k] = ip[k] ? 1 : 0;
    }
}

// ---------------- 1) L2 normalize rows of x and y ----------------
__global__ void norm_kernel(const float* __restrict__ x, const float* __restrict__ y) {
    int row  = (blockIdx.x * blockDim.x + threadIdx.x) >> 5;
    int lane = threadIdx.x & 31;
    if (row >= XROWS + YROWS) return;
    const float* src;
    float* dst;
    if (row < XROWS) { src = x + (size_t)row * HDIM;           dst = g_xn + (size_t)row * HDIM; }
    else             { src = y + (size_t)(row - XROWS) * HDIM; dst = g_yn + (size_t)(row - XROWS) * HDIM; }

    const float4* s4 = (const float4*)src;
    float4 v[4];
    float ss = 0.f;
#pragma unroll
    for (int q = 0; q < 4; q++) {
        v[q] = s4[lane + 32 * q];
        ss += v[q].x * v[q].x + v[q].y * v[q].y + v[q].z * v[q].z + v[q].w * v[q].w;
    }
#pragma unroll
    for (int o = 16; o; o >>= 1) ss += __shfl_xor_sync(0xffffffffu, ss, o);
    float inv = 1.0f / fmaxf(sqrtf(ss), 1e-12f);
    float4* d4 = (float4*)dst;
#pragma unroll
    for (int q = 0; q < 4; q++) {
        float4 w = v[q];
        w.x *= inv; w.y *= inv; w.z *= inv; w.w *= inv;
        d4[lane + 32 * q] = w;
    }
}

// ---------------- 2) scores GEMM: C[12544,2048] = Xn (12544x512) * Yn^T ----
// 128x128x16 tile, 256 threads, 8x8 micro-tile, packed fma.rn.f32x2 (Blackwell).
#define BM 128
#define BN 128
#define BK 16
#define SSTRIDE 132   // smem row stride (floats)

__device__ __forceinline__ unsigned long long pack_dup(float x) {
    unsigned long long r;
    asm("mov.b64 %0, {%1, %1};" : "=l"(r) : "f"(x));
    return r;
}
__device__ __forceinline__ void ffma2(unsigned long long& d, unsigned long long a,
                                      unsigned long long b) {
    asm("fma.rn.f32x2 %0, %1, %2, %0;" : "+l"(d) : "l"(a), "l"(b));
}

__global__ __launch_bounds__(256) void gemm_kernel() {
    __shared__ float As[BK * SSTRIDE];
    __shared__ float Bs[BK * SSTRIDE];
    const int tid = threadIdx.x;
    const int m0 = blockIdx.y * BM;
    const int n0 = blockIdx.x * BN;

    const int lrow = tid >> 1;            // 0..127
    const int kb   = (tid & 1) * 8;       // 0 or 8
    const int ty   = tid >> 4;            // 0..15 -> row group
    const int tx   = tid & 15;            // 0..15 -> col pairs

    const float* Aptr = g_xn + (size_t)(m0 + lrow) * HDIM + kb;
    const float* Bptr = g_yn + (size_t)(n0 + lrow) * HDIM + kb;

    unsigned long long acc[8][4];
#pragma unroll
    for (int r = 0; r < 8; r++)
#pragma unroll
        for (int g = 0; g < 4; g++) acc[r][g] = 0ULL;

    float4 af0 = *(const float4*)Aptr;
    float4 af1 = *(const float4*)(Aptr + 4);
    float4 bf0 = *(const float4*)Bptr;
    float4 bf1 = *(const float4*)(Bptr + 4);

    const int NT = HDIM / BK;   // 32 k-tiles
    for (int kt = 0; kt < NT; kt++) {
        As[(kb + 0) * SSTRIDE + lrow] = af0.x;
        As[(kb + 1) * SSTRIDE + lrow] = af0.y;
        As[(kb + 2) * SSTRIDE + lrow] = af0.z;
        As[(kb + 3) * SSTRIDE + lrow] = af0.w;
        As[(kb + 4) * SSTRIDE + lrow] = af1.x;
        As[(kb + 5) * SSTRIDE + lrow] = af1.y;
        As[(kb + 6) * SSTRIDE + lrow] = af1.z;
        As[(kb + 7) * SSTRIDE + lrow] = af1.w;
        Bs[(kb + 0) * SSTRIDE + lrow] = bf0.x;
        Bs[(kb + 1) * SSTRIDE + lrow] = bf0.y;
        Bs[(kb + 2) * SSTRIDE + lrow] = bf0.z;
        Bs[(kb + 3) * SSTRIDE + lrow] = bf0.w;
        Bs[(kb + 4) * SSTRIDE + lrow] = bf1.x;
        Bs[(kb + 5) * SSTRIDE + lrow] = bf1.y;
        Bs[(kb + 6) * SSTRIDE + lrow] = bf1.z;
        Bs[(kb + 7) * SSTRIDE + lrow] = bf1.w;
        __syncthreads();
        if (kt + 1 < NT) {
            const float* an = Aptr + (kt + 1) * BK;
            const float* bn = Bptr + (kt + 1) * BK;
            af0 = *(const float4*)an; af1 = *(const float4*)(an + 4);
            bf0 = *(const float4*)bn; bf1 = *(const float4*)(bn + 4);
        }
#pragma unroll
        for (int k = 0; k < BK; k++) {
            const float* arow = &As[k * SSTRIDE + ty * 8];
            float4 a01 = *(const float4*)(arow);
            float4 a23 = *(const float4*)(arow + 4);
            const float* brow = &Bs[k * SSTRIDE];
            unsigned long long b0 = *(const unsigned long long*)(brow + tx * 2);
            unsigned long long b1 = *(const unsigned long long*)(brow + 32 + tx * 2);
            unsigned long long b2 = *(const unsigned long long*)(brow + 64 + tx * 2);
            unsigned long long b3 = *(const unsigned long long*)(brow + 96 + tx * 2);
            float av[8] = {a01.x, a01.y, a01.z, a01.w, a23.x, a23.y, a23.z, a23.w};
#pragma unroll
            for (int r = 0; r < 8; r++) {
                unsigned long long aa = pack_dup(av[r]);
                ffma2(acc[r][0], aa, b0);
                ffma2(acc[r][1], aa, b1);
                ffma2(acc[r][2], aa, b2);
                ffma2(acc[r][3], aa, b3);
            }
        }
        __syncthreads();
    }

#pragma unroll
    for (int r = 0; r < 8; r++) {
        float* crow = &g_scores[(size_t)(m0 + ty * 8 + r) * YROWS + n0];
#pragma unroll
        for (int g = 0; g < 4; g++) {
            *(unsigned long long*)(crow + g * 32 + tx * 2) = acc[r][g];
        }
    }
}

// ---------------- 3) per-pair Sinkhorn (base-2 log domain, register-resident Z) ----
// Thread t<50 owns row t (33 regs); thread t<33 owns col t (50 regs).
__global__ __launch_bounds__(64) void sinkhorn_kernel(const float* __restrict__ dbim,
                                                      const float* __restrict__ dblang,
                                                      float* __restrict__ out_match) {
    __shared__ float Zr[MP1 * LP1];
    __shared__ float U2[MP1];
    __shared__ float V2[LP1];
    __shared__ unsigned char mc[LP1];
    __shared__ float sh_ns;
    __shared__ float wsum[2];

    const int bi = blockIdx.x;
    const int i = bi >> 6;       // image 0..255
    const int j = bi & 63;       // lang  0..63
    const int tid = threadIdx.x; // 64 threads

    if (tid < L_TOK) mc[tid] = g_mask[j * L_TOK + tid];
    if (tid == L_TOK) mc[L_TOK] = 0;
    __syncthreads();
    if (tid == 0) {
        int valid = 0;
        for (int c = 0; c < L_TOK; c++) valid += mc[c] ? 0 : 1;
        sh_ns = (float)valid;
    }

    const float a_im   = fminf(fmaxf(dbim[0],   -1.f), 1.f);
    const float a_lang = fminf(fmaxf(dblang[0], -1.f), 1.f);
    const float SC    = INVREG * LOG2E;   // score -> base-2 scaled
    const float binc2 = a_im   * SC;      // col 32 (all rows incl. corner)
    const float binr2 = a_lang * SC;      // row 49, cols < 32

    // build Zr in smem (base-2 scaled; NEGV sentinel on masked cols)
    // incremental (r,c) update: stride 64 = LP1 + 31
    const float* sbase = g_scores + (size_t)i * M_REG * YROWS + (size_t)j * L_TOK;
    {
        int r = tid / LP1, c = tid - r * LP1;
        for (int idx = tid; idx < MP1 * LP1; idx += 64) {
            float val;
            if (c < L_TOK) {
                if (mc[c])          val = NEGV;
                else if (r < M_REG) val = sbase[(size_t)r * YROWS + c] * SC;
                else                val = binr2;
            } else {
                val = binc2;
            }
            Zr[idx] = val;
            r += 1; c += 31;
            if (c >= LP1) { c -= LP1; r += 1; }
        }
    }
    if (tid < LP1) V2[tid] = (tid < L_TOK && mc[tid]) ? NEGV : 0.f;
    __syncthreads();

    // load register-resident copies
    float zrow[LP1];
    if (tid < MP1) {
#pragma unroll
        for (int c = 0; c < LP1; c++) zrow[c] = Zr[tid * LP1 + c];
    }
    float zcol[MP1];
    const bool colActive = (tid < LP1) && !(tid < L_TOK && mc[tid]);
    if (tid < LP1) {
#pragma unroll
        for (int r = 0; r < MP1; r++) zcol[r] = Zr[r * LP1 + tid];
    }

    const float ns = sh_ns;
    const float n2 = -__log2f((float)M_REG + ns);              // norm * log2e
    const float lmu2 = (tid < M_REG) ? n2 : (__log2f(ns) + n2);
    const float lnu2 = (tid < L_TOK) ? n2 : (__log2f((float)M_REG) + n2);

    for (int it = 0; it < ITERS; it++) {
        // row pass: U2[r] = lmu2 - LSE2_c(zrow + V2)
        if (tid < MP1) {
            float mx = -INFINITY;
#pragma unroll
            for (int c = 0; c < LP1; c++) mx = fmaxf(mx, zrow[c] + V2[c]);
            float s = 0.f;
#pragma unroll
            for (int c = 0; c < LP1; c++) s += ex2f(zrow[c] + V2[c] - mx);
            U2[tid] = lmu2 - mx - __log2f(s);
        }
        __syncthreads();
        // col pass: V2[c] = lnu2 - LSE2_r(zcol + U2)   (masked cols stay NEGV)
        if (colActive) {
            float mx = -INFINITY;
#pragma unroll
            for (int r = 0; r < MP1; r++) mx = fmaxf(mx, zcol[r] + U2[r]);
            float s = 0.f;
#pragma unroll
            for (int r = 0; r < MP1; r++) s += ex2f(zcol[r] + U2[r] - mx);
            V2[tid] = lnu2 - mx - __log2f(s);
        }
        __syncthreads();
    }

    // finalize: Zm = exp2(Zr + U2 + V2 - n2); matching output + ot partial
    float part = 0.f;
    {
        int r = tid / LP1, c = tid - r * LP1;
        for (int idx = tid; idx < MP1 * LP1; idx += 64) {
            float zr = Zr[idx];
            float zm = ex2f(zr + U2[r] + V2[c] - n2);
            if (out_match) out_match[(size_t)bi * (MP1 * LP1) + idx] = zm;
            if (r < M_REG && c < L_TOK) part += zr * zm;   // zr = score*10*log2e
            r += 1; c += 31;
            if (c >= LP1) { c -= LP1; r += 1; }
        }
    }
#pragma unroll
    for (int o = 16; o; o >>= 1) part += __shfl_down_sync(0xffffffffu, part, o);
    if ((tid & 31) == 0) wsum[tid >> 5] = part;
    __syncthreads();
    // ot = sum(score*zm)/TEMP = part * LN2 * REG / TEMP, and REG/TEMP = 1
    if (tid == 0) g_ot[bi] = (wsum[0] + wsum[1]) * LN2;
}

// ---------------- 4) InfoNCE loss over ot_scores (256x64) ----------------
__global__ __launch_bounds__(256) void loss_kernel(float* __restrict__ out_loss) {
    __shared__ float sl[8], si[8];
    const int i = threadIdx.x;        // image index 0..255
    const int grp = i >> 2;           // lang of image i
    const float* row = g_ot + i * N_LANG;
    const float pos = row[grp];

    float mx = -INFINITY;
    for (int c = 0; c < N_LANG; c++) mx = fmaxf(mx, row[c]);
    float s = 0.f;
    for (int c = 0; c < N_LANG; c++) s += __expf(row[c] - mx);
    float t_lang = pos - (mx + __logf(s));

    float mx2 = -INFINITY;
    for (int k = 0; k < N_IMG; k++) {
        if (((k >> 2) != grp) || (k == i)) mx2 = fmaxf(mx2, g_ot[k * N_LANG + grp]);
    }
    float s2 = 0.f;
    for (int k = 0; k < N_IMG; k++) {
        if (((k >> 2) != grp) || (k == i)) s2 += __expf(g_ot[k * N_LANG + grp] - mx2);
    }
    float t_im = pos - (mx2 + __logf(s2));

#pragma unroll
    for (int o = 16; o; o >>= 1) {
        t_lang += __shfl_down_sync(0xffffffffu, t_lang, o);
        t_im   += __shfl_down_sync(0xffffffffu, t_im, o);
    }
    if ((i & 31) == 0) { sl[i >> 5] = t_lang; si[i >> 5] = t_im; }
    __syncthreads();
    if (i == 0) {
        float a = 0.f, b = 0.f;
        for (int w = 0; w < 8; w++) { a += sl[w]; b += si[w]; }
        *out_loss = -0.5f * (a + b) / (float)N_IMG;
    }
}

// ---------------- launcher ----------------
extern "C" void kernel_launch(void* const* d_in, const int* in_sizes, int n_in,
                              void* d_out, int out_size) {
    const float* x      = (const float*)d_in[0];
    const float* y      = (const float*)d_in[1];
    const float* dbim   = (const float*)d_in[2];
    const float* dblang = (const float*)d_in[3];
    const void*  ymask  = d_in[4];

    float* outF = (float*)d_out;
    const long long MATCH = (long long)NB * MP1 * LP1;   // 27,033,600
    float* matchPtr = outF;
    float* lossPtr;
    if ((long long)out_size >= MATCH + 1) lossPtr = outF + MATCH;
    else if (out_size == 1)               { lossPtr = outF; matchPtr = nullptr; }
    else                                   lossPtr = outF;  // fallback

    decode_mask_kernel<<<1, 256>>>(ymask);
    {   // normalize
        int rows = XROWS + YROWS;
        int threads = 256;
        int blocks = (rows * 32 + threads - 1) / threads;
        norm_kernel<<<blocks, threads>>>(x, y);
    }
    {   // GEMM: 12544/128 = 98, 2048/128 = 16
        dim3 grid(YROWS / BN, XROWS / BM);
        gemm_kernel<<<grid, 256>>>();
    }
    {   // sinkhorn per (image, lang) pair
        sinkhorn_kernel<<<NB, 64>>>(dbim, dblang, matchPtr);
    }
    {   // loss
        loss_kernel<<<1, 256>>>(lossPtr);
    }
}

// round 7
// speedup vs baseline: 1.5766x; 1.1799x over previous
#include <cuda_runtime.h>
#include <cuda_bf16.h>
#include <math.h>

// ---------------- problem constants ----------------
#define N_LANG   64
#define N_EX     4
#define N_IMG    (N_LANG * N_EX)        // 256
#define M_REG    49
#define L_TOK    32
#define HDIM     512
#define MP1      (M_REG + 1)            // 50
#define LP1      (L_TOK + 1)            // 33
#define NB       (N_IMG * N_LANG)       // 16384 batch items
#define XROWS    (N_IMG * M_REG)        // 12544
#define YROWS    (N_LANG * L_TOK)       // 2048
#define REG      0.1f
#define INVREG   10.0f
#define TEMP     0.1f
#define ITERS    10
#define NEGV     (-1.0e7f)              // sentinel (exp2 -> 0)
#define LOG2E    1.4426950408889634f
#define LN2      0.6931471805599453f

// scratch (static device allocations are the sanctioned workaround)
__device__ float g_xn[(size_t)XROWS * HDIM];      // 25.7 MB
__device__ float g_yn[(size_t)YROWS * HDIM];      //  4.2 MB
__device__ float g_scores[(size_t)XROWS * YROWS]; // 102.8 MB  C[row, col]
__device__ float g_ot[NB];                        // 64 KB
__device__ unsigned char g_mask[YROWS];           // decoded y_mask (2048 bytes)

__device__ __forceinline__ float ex2f(float x) {
    float r; asm("ex2.approx.ftz.f32 %0, %1;" : "=f"(r) : "f"(x)); return r;
}

// ---------------- 0) decode y_mask regardless of storage dtype ----------------
__global__ void decode_mask_kernel(const void* __restrict__ p) {
    __shared__ int bad;
    if (threadIdx.x == 0) bad = 0;
    __syncthreads();
    const int* ip = (const int*)p;
    for (int k = threadIdx.x; k < 512; k += blockDim.x) {
        int w = ip[k];
        if (w != 0 && w != 1 && w != 0x3f800000) atomicOr(&bad, 1);
    }
    __syncthreads();
    if (bad) {  // byte-encoded mask
        const unsigned char* bp = (const unsigned char*)p;
        for (int k = threadIdx.x; k < YROWS; k += blockDim.x)
            g_mask[k] = bp[k] ? 1 : 0;
    } else {    // 4-byte-encoded mask (int32 0/1 or float32 0.0/1.0)
        for (int k = threadIdx.x; k < YROWS; k += blockDim.x)
            g_mask[k] = ip[k] ? 1 : 0;
    }
}

// ---------------- 1) L2 normalize rows of x and y ----------------
__global__ void norm_kernel(const float* __restrict__ x, const float* __restrict__ y) {
    int row  = (blockIdx.x * blockDim.x + threadIdx.x) >> 5;
    int lane = threadIdx.x & 31;
    if (row >= XROWS + YROWS) return;
    const float* src;
    float* dst;
    if (row < XROWS) { src = x + (size_t)row * HDIM;           dst = g_xn + (size_t)row * HDIM; }
    else             { src = y + (size_t)(row - XROWS) * HDIM; dst = g_yn + (size_t)(row - XROWS) * HDIM; }

    const float4* s4 = (const float4*)src;
    float4 v[4];
    float ss = 0.f;
#pragma unroll
    for (int q = 0; q < 4; q++) {
        v[q] = s4[lane + 32 * q];
        ss += v[q].x * v[q].x + v[q].y * v[q].y + v[q].z * v[q].z + v[q].w * v[q].w;
    }
#pragma unroll
    for (int o = 16; o; o >>= 1) ss += __shfl_xor_sync(0xffffffffu, ss, o);
    float inv = 1.0f / fmaxf(sqrtf(ss), 1e-12f);
    float4* d4 = (float4*)dst;
#pragma unroll
    for (int q = 0; q < 4; q++) {
        float4 w = v[q];
        w.x *= inv; w.y *= inv; w.z *= inv; w.w *= inv;
        d4[lane + 32 * q] = w;
    }
}

// ---------------- 2) scores GEMM: C[12544,2048] = Xn (12544x512) * Yn^T ----
// 128x128x16 tile, 256 threads, 8x8 micro-tile, packed fma.rn.f32x2 (Blackwell).
#define BM 128
#define BN 128
#define BK 16
#define SSTRIDE 132   // smem row stride (floats)

__device__ __forceinline__ unsigned long long pack_dup(float x) {
    unsigned long long r;
    asm("mov.b64 %0, {%1, %1};" : "=l"(r) : "f"(x));
    return r;
}
__device__ __forceinline__ void ffma2(unsigned long long& d, unsigned long long a,
                                      unsigned long long b) {
    asm("fma.rn.f32x2 %0, %1, %2, %0;" : "+l"(d) : "l"(a), "l"(b));
}

__global__ __launch_bounds__(256) void gemm_kernel() {
    __shared__ float As[BK * SSTRIDE];
    __shared__ float Bs[BK * SSTRIDE];
    const int tid = threadIdx.x;
    const int m0 = blockIdx.y * BM;
    const int n0 = blockIdx.x * BN;

    const int lrow = tid >> 1;            // 0..127
    const int kb   = (tid & 1) * 8;       // 0 or 8
    const int ty   = tid >> 4;            // 0..15 -> row group
    const int tx   = tid & 15;            // 0..15 -> col pairs

    const float* Aptr = g_xn + (size_t)(m0 + lrow) * HDIM + kb;
    const float* Bptr = g_yn + (size_t)(n0 + lrow) * HDIM + kb;

    unsigned long long acc[8][4];
#pragma unroll
    for (int r = 0; r < 8; r++)
#pragma unroll
        for (int g = 0; g < 4; g++) acc[r][g] = 0ULL;

    float4 af0 = *(const float4*)Aptr;
    float4 af1 = *(const float4*)(Aptr + 4);
    float4 bf0 = *(const float4*)Bptr;
    float4 bf1 = *(const float4*)(Bptr + 4);

    const int NT = HDIM / BK;   // 32 k-tiles
    for (int kt = 0; kt < NT; kt++) {
        As[(kb + 0) * SSTRIDE + lrow] = af0.x;
        As[(kb + 1) * SSTRIDE + lrow] = af0.y;
        As[(kb + 2) * SSTRIDE + lrow] = af0.z;
        As[(kb + 3) * SSTRIDE + lrow] = af0.w;
        As[(kb + 4) * SSTRIDE + lrow] = af1.x;
        As[(kb + 5) * SSTRIDE + lrow] = af1.y;
        As[(kb + 6) * SSTRIDE + lrow] = af1.z;
        As[(kb + 7) * SSTRIDE + lrow] = af1.w;
        Bs[(kb + 0) * SSTRIDE + lrow] = bf0.x;
        Bs[(kb + 1) * SSTRIDE + lrow] = bf0.y;
        Bs[(kb + 2) * SSTRIDE + lrow] = bf0.z;
        Bs[(kb + 3) * SSTRIDE + lrow] = bf0.w;
        Bs[(kb + 4) * SSTRIDE + lrow] = bf1.x;
        Bs[(kb + 5) * SSTRIDE + lrow] = bf1.y;
        Bs[(kb + 6) * SSTRIDE + lrow] = bf1.z;
        Bs[(kb + 7) * SSTRIDE + lrow] = bf1.w;
        __syncthreads();
        if (kt + 1 < NT) {
            const float* an = Aptr + (kt + 1) * BK;
            const float* bn = Bptr + (kt + 1) * BK;
            af0 = *(const float4*)an; af1 = *(const float4*)(an + 4);
            bf0 = *(const float4*)bn; bf1 = *(const float4*)(bn + 4);
        }
#pragma unroll
        for (int k = 0; k < BK; k++) {
            const float* arow = &As[k * SSTRIDE + ty * 8];
            float4 a01 = *(const float4*)(arow);
            float4 a23 = *(const float4*)(arow + 4);
            const float* brow = &Bs[k * SSTRIDE];
            unsigned long long b0 = *(const unsigned long long*)(brow + tx * 2);
            unsigned long long b1 = *(const unsigned long long*)(brow + 32 + tx * 2);
            unsigned long long b2 = *(const unsigned long long*)(brow + 64 + tx * 2);
            unsigned long long b3 = *(const unsigned long long*)(brow + 96 + tx * 2);
            float av[8] = {a01.x, a01.y, a01.z, a01.w, a23.x, a23.y, a23.z, a23.w};
#pragma unroll
            for (int r = 0; r < 8; r++) {
                unsigned long long aa = pack_dup(av[r]);
                ffma2(acc[r][0], aa, b0);
                ffma2(acc[r][1], aa, b1);
                ffma2(acc[r][2], aa, b2);
                ffma2(acc[r][3], aa, b3);
            }
        }
        __syncthreads();
    }

#pragma unroll
    for (int r = 0; r < 8; r++) {
        float* crow = &g_scores[(size_t)(m0 + ty * 8 + r) * YROWS + n0];
#pragma unroll
        for (int g = 0; g < 4; g++) {
            *(unsigned long long*)(crow + g * 32 + tx * 2) = acc[r][g];
        }
    }
}

// ---------------- 3) per-pair Sinkhorn (base-2 log domain) ----------------
// Row pass: thread t<50 keeps its row in registers (33 regs).
// Col pass: thread t<33 re-reads its column from smem (conflict-free:
// bank of Zr[r*33+t] is (r+t) mod 32 -> distinct across active threads).
// zcol register array removed to cut regs ~150 -> ~70 (occupancy was 18%).
__global__ __launch_bounds__(64, 12) void sinkhorn_kernel(const float* __restrict__ dbim,
                                                          const float* __restrict__ dblang,
                                                          float* __restrict__ out_match) {
    __shared__ float Zr[MP1 * LP1];
    __shared__ float U2[MP1];
    __shared__ float V2[LP1];
    __shared__ unsigned char mc[LP1];
    __shared__ float sh_ns;
    __shared__ float wsum[2];

    const int bi = blockIdx.x;
    const int i = bi >> 6;       // image 0..255
    const int j = bi & 63;       // lang  0..63
    const int tid = threadIdx.x; // 64 threads

    if (tid < L_TOK) mc[tid] = g_mask[j * L_TOK + tid];
    if (tid == L_TOK) mc[L_TOK] = 0;
    __syncthreads();
    if (tid == 0) {
        int valid = 0;
        for (int c = 0; c < L_TOK; c++) valid += mc[c] ? 0 : 1;
        sh_ns = (float)valid;
    }

    const float a_im   = fminf(fmaxf(dbim[0],   -1.f), 1.f);
    const float a_lang = fminf(fmaxf(dblang[0], -1.f), 1.f);
    const float SC    = INVREG * LOG2E;   // score -> base-2 scaled
    const float binc2 = a_im   * SC;      // col 32 (all rows incl. corner)
    const float binr2 = a_lang * SC;      // row 49, cols < 32

    // build Zr in smem (base-2 scaled; NEGV sentinel on masked cols)
    // incremental (r,c) update: stride 64 = LP1 + 31
    const float* sbase = g_scores + (size_t)i * M_REG * YROWS + (size_t)j * L_TOK;
    {
        int r = tid / LP1, c = tid - r * LP1;
        for (int idx = tid; idx < MP1 * LP1; idx += 64) {
            float val;
            if (c < L_TOK) {
                if (mc[c])          val = NEGV;
                else if (r < M_REG) val = sbase[(size_t)r * YROWS + c] * SC;
                else                val = binr2;
            } else {
                val = binc2;
            }
            Zr[idx] = val;
            r += 1; c += 31;
            if (c >= LP1) { c -= LP1; r += 1; }
        }
    }
    if (tid < LP1) V2[tid] = (tid < L_TOK && mc[tid]) ? NEGV : 0.f;
    __syncthreads();

    // row data register-resident (33 regs)
    float zrow[LP1];
    if (tid < MP1) {
#pragma unroll
        for (int c = 0; c < LP1; c++) zrow[c] = Zr[tid * LP1 + c];
    }
    const bool colActive = (tid < LP1) && !(tid < L_TOK && mc[tid]);

    const float ns = sh_ns;
    const float n2 = -__log2f((float)M_REG + ns);              // norm * log2e
    const float lmu2 = (tid < M_REG) ? n2 : (__log2f(ns) + n2);
    const float lnu2 = (tid < L_TOK) ? n2 : (__log2f((float)M_REG) + n2);

    for (int it = 0; it < ITERS; it++) {
        // row pass: U2[r] = lmu2 - LSE2_c(zrow + V2)
        if (tid < MP1) {
            float mx = -INFINITY;
#pragma unroll
            for (int c = 0; c < LP1; c++) mx = fmaxf(mx, zrow[c] + V2[c]);
            float s = 0.f;
#pragma unroll
            for (int c = 0; c < LP1; c++) s += ex2f(zrow[c] + V2[c] - mx);
            U2[tid] = lmu2 - mx - __log2f(s);
        }
        __syncthreads();
        // col pass: V2[c] = lnu2 - LSE2_r(Zr[:,c] + U2)   (masked cols stay NEGV)
        if (colActive) {
            float mx = -INFINITY;
#pragma unroll
            for (int r = 0; r < MP1; r++) mx = fmaxf(mx, Zr[r * LP1 + tid] + U2[r]);
            float s = 0.f;
#pragma unroll
            for (int r = 0; r < MP1; r++) s += ex2f(Zr[r * LP1 + tid] + U2[r] - mx);
            V2[tid] = lnu2 - mx - __log2f(s);
        }
        __syncthreads();
    }

    // finalize: Zm = exp2(Zr + U2 + V2 - n2); matching output + ot partial
    float part = 0.f;
    {
        int r = tid / LP1, c = tid - r * LP1;
        for (int idx = tid; idx < MP1 * LP1; idx += 64) {
            float zr = Zr[idx];
            float zm = ex2f(zr + U2[r] + V2[c] - n2);
            if (out_match) out_match[(size_t)bi * (MP1 * LP1) + idx] = zm;
            if (r < M_REG && c < L_TOK) part += zr * zm;   // zr = score*10*log2e
            r += 1; c += 31;
            if (c >= LP1) { c -= LP1; r += 1; }
        }
    }
#pragma unroll
    for (int o = 16; o; o >>= 1) part += __shfl_down_sync(0xffffffffu, part, o);
    if ((tid & 31) == 0) wsum[tid >> 5] = part;
    __syncthreads();
    // ot = sum(score*zm)/TEMP = part * LN2 * REG / TEMP, and REG/TEMP = 1
    if (tid == 0) g_ot[bi] = (wsum[0] + wsum[1]) * LN2;
}

// ---------------- 4) InfoNCE loss over ot_scores (256x64) ----------------
__global__ __launch_bounds__(256) void loss_kernel(float* __restrict__ out_loss) {
    __shared__ float sl[8], si[8];
    const int i = threadIdx.x;        // image index 0..255
    const int grp = i >> 2;           // lang of image i
    const float* row = g_ot + i * N_LANG;
    const float pos = row[grp];

    float mx = -INFINITY;
    for (int c = 0; c < N_LANG; c++) mx = fmaxf(mx, row[c]);
    float s = 0.f;
    for (int c = 0; c < N_LANG; c++) s += __expf(row[c] - mx);
    float t_lang = pos - (mx + __logf(s));

    float mx2 = -INFINITY;
    for (int k = 0; k < N_IMG; k++) {
        if (((k >> 2) != grp) || (k == i)) mx2 = fmaxf(mx2, g_ot[k * N_LANG + grp]);
    }
    float s2 = 0.f;
    for (int k = 0; k < N_IMG; k++) {
        if (((k >> 2) != grp) || (k == i)) s2 += __expf(g_ot[k * N_LANG + grp] - mx2);
    }
    float t_im = pos - (mx2 + __logf(s2));

#pragma unroll
    for (int o = 16; o; o >>= 1) {
        t_lang += __shfl_down_sync(0xffffffffu, t_lang, o);
        t_im   += __shfl_down_sync(0xffffffffu, t_im, o);
    }
    if ((i & 31) == 0) { sl[i >> 5] = t_lang; si[i >> 5] = t_im; }
    __syncthreads();
    if (i == 0) {
        float a = 0.f, b = 0.f;
        for (int w = 0; w < 8; w++) { a += sl[w]; b += si[w]; }
        *out_loss = -0.5f * (a + b) / (float)N_IMG;
    }
}

// ---------------- launcher ----------------
extern "C" void kernel_launch(void* const* d_in, const int* in_sizes, int n_in,
                              void* d_out, int out_size) {
    const float* x      = (const float*)d_in[0];
    const float* y      = (const float*)d_in[1];
    const float* dbim   = (const float*)d_in[2];
    const float* dblang = (const float*)d_in[3];
    const void*  ymask  = d_in[4];

    float* outF = (float*)d_out;
    const long long MATCH = (long long)NB * MP1 * LP1;   // 27,033,600
    float* matchPtr = outF;
    float* lossPtr;
    if ((long long)out_size >= MATCH + 1) lossPtr = outF + MATCH;
    else if (out_size == 1)               { lossPtr = outF; matchPtr = nullptr; }
    else                                   lossPtr = outF;  // fallback

    decode_mask_kernel<<<1, 256>>>(ymask);
    {   // normalize
        int rows = XROWS + YROWS;
        int threads = 256;
        int blocks = (rows * 32 + threads - 1) / threads;
        norm_kernel<<<blocks, threads>>>(x, y);
    }
    {   // GEMM: 12544/128 = 98, 2048/128 = 16
        dim3 grid(YROWS / BN, XROWS / BM);
        gemm_kernel<<<grid, 256>>>();
    }
    {   // sinkhorn per (image, lang) pair
        sinkhorn_kernel<<<NB, 64>>>(dbim, dblang, matchPtr);
    }
    {   // loss
        loss_kernel<<<1, 256>>>(lossPtr);
    }
}

// round 9
// speedup vs baseline: 1.6899x; 1.0719x over previous
#include <cuda_runtime.h>
#include <cuda_bf16.h>
#include <math.h>

// ---------------- problem constants ----------------
#define N_LANG   64
#define N_EX     4
#define N_IMG    (N_LANG * N_EX)        // 256
#define M_REG    49
#define L_TOK    32
#define HDIM     512
#define MP1      (M_REG + 1)            // 50
#define LP1      (L_TOK + 1)            // 33
#define NB       (N_IMG * N_LANG)       // 16384 batch items
#define XROWS    (N_IMG * M_REG)        // 12544
#define YROWS    (N_LANG * L_TOK)       // 2048
#define REG      0.1f
#define INVREG   10.0f
#define TEMP     0.1f
#define ITERS    10
#define NEGV     (-1.0e7f)              // sentinel (exp2 -> 0)
#define LOG2E    1.4426950408889634f
#define LN2      0.6931471805599453f

// scratch (static device allocations are the sanctioned workaround)
__device__ float g_xn[(size_t)XROWS * HDIM];      // 25.7 MB
__device__ float g_yn[(size_t)YROWS * HDIM];      //  4.2 MB
__device__ float g_scores[(size_t)XROWS * YROWS]; // 102.8 MB  C[row, col]
__device__ float g_ot[NB];                        // 64 KB
__device__ unsigned char g_mask[YROWS];           // decoded y_mask (2048 bytes)

__device__ __forceinline__ float ex2f(float x) {
    float r; asm("ex2.approx.ftz.f32 %0, %1;" : "=f"(r) : "f"(x)); return r;
}
__device__ __forceinline__ float rcpf(float x) {
    float r; asm("rcp.approx.ftz.f32 %0, %1;" : "=f"(r) : "f"(x)); return r;
}

// ---------------- 0) decode y_mask regardless of storage dtype ----------------
__global__ void decode_mask_kernel(const void* __restrict__ p) {
    __shared__ int bad;
    if (threadIdx.x == 0) bad = 0;
    __syncthreads();
    const int* ip = (const int*)p;
    for (int k = threadIdx.x; k < 512; k += blockDim.x) {
        int w = ip[k];
        if (w != 0 && w != 1 && w != 0x3f800000) atomicOr(&bad, 1);
    }
    __syncthreads();
    if (bad) {  // byte-encoded mask
        const unsigned char* bp = (const unsigned char*)p;
        for (int k = threadIdx.x; k < YROWS; k += blockDim.x)
            g_mask[k] = bp[k] ? 1 : 0;
    } else {    // 4-byte-encoded mask (int32 0/1 or float32 0.0/1.0)
        for (int k = threadIdx.x; k < YROWS; k += blockDim.x)
            g_mask[k] = ip[k] ? 1 : 0;
    }
}

// ---------------- 1) L2 normalize rows of x and y ----------------
__global__ void norm_kernel(const float* __restrict__ x, const float* __restrict__ y) {
    int row  = (blockIdx.x * blockDim.x + threadIdx.x) >> 5;
    int lane = threadIdx.x & 31;
    if (row >= XROWS + YROWS) return;
    const float* src;
    float* dst;
    if (row < XROWS) { src = x + (size_t)row * HDIM;           dst = g_xn + (size_t)row * HDIM; }
    else             { src = y + (size_t)(row - XROWS) * HDIM; dst = g_yn + (size_t)(row - XROWS) * HDIM; }

    const float4* s4 = (const float4*)src;
    float4 v[4];
    float ss = 0.f;
#pragma unroll
    for (int q = 0; q < 4; q++) {
        v[q] = s4[lane + 32 * q];
        ss += v[q].x * v[q].x + v[q].y * v[q].y + v[q].z * v[q].z + v[q].w * v[q].w;
    }
#pragma unroll
    for (int o = 16; o; o >>= 1) ss += __shfl_xor_sync(0xffffffffu, ss, o);
    float inv = 1.0f / fmaxf(sqrtf(ss), 1e-12f);
    float4* d4 = (float4*)dst;
#pragma unroll
    for (int q = 0; q < 4; q++) {
        float4 w = v[q];
        w.x *= inv; w.y *= inv; w.z *= inv; w.w *= inv;
        d4[lane + 32 * q] = w;
    }
}

// ---------------- 2) scores GEMM: C[12544,2048] = Xn (12544x512) * Yn^T ----
// 128x128x16 tile, 256 threads, 8x8 micro-tile, packed fma.rn.f32x2 (Blackwell).
#define BM 128
#define BN 128
#define BK 16
#define SSTRIDE 132   // smem row stride (floats)

__device__ __forceinline__ unsigned long long pack_dup(float x) {
    unsigned long long r;
    asm("mov.b64 %0, {%1, %1};" : "=l"(r) : "f"(x));
    return r;
}
__device__ __forceinline__ void ffma2(unsigned long long& d, unsigned long long a,
                                      unsigned long long b) {
    asm("fma.rn.f32x2 %0, %1, %2, %0;" : "+l"(d) : "l"(a), "l"(b));
}

__global__ __launch_bounds__(256) void gemm_kernel() {
    __shared__ float As[BK * SSTRIDE];
    __shared__ float Bs[BK * SSTRIDE];
    const int tid = threadIdx.x;
    const int m0 = blockIdx.y * BM;
    const int n0 = blockIdx.x * BN;

    const int lrow = tid >> 1;            // 0..127
    const int kb   = (tid & 1) * 8;       // 0 or 8
    const int ty   = tid >> 4;            // 0..15 -> row group
    const int tx   = tid & 15;            // 0..15 -> col pairs

    const float* Aptr = g_xn + (size_t)(m0 + lrow) * HDIM + kb;
    const float* Bptr = g_yn + (size_t)(n0 + lrow) * HDIM + kb;

    unsigned long long acc[8][4];
#pragma unroll
    for (int r = 0; r < 8; r++)
#pragma unroll
        for (int g = 0; g < 4; g++) acc[r][g] = 0ULL;

    float4 af0 = *(const float4*)Aptr;
    float4 af1 = *(const float4*)(Aptr + 4);
    float4 bf0 = *(const float4*)Bptr;
    float4 bf1 = *(const float4*)(Bptr + 4);

    const int NT = HDIM / BK;   // 32 k-tiles
    for (int kt = 0; kt < NT; kt++) {
        As[(kb + 0) * SSTRIDE + lrow] = af0.x;
        As[(kb + 1) * SSTRIDE + lrow] = af0.y;
        As[(kb + 2) * SSTRIDE + lrow] = af0.z;
        As[(kb + 3) * SSTRIDE + lrow] = af0.w;
        As[(kb + 4) * SSTRIDE + lrow] = af1.x;
        As[(kb + 5) * SSTRIDE + lrow] = af1.y;
        As[(kb + 6) * SSTRIDE + lrow] = af1.z;
        As[(kb + 7) * SSTRIDE + lrow] = af1.w;
        Bs[(kb + 0) * SSTRIDE + lrow] = bf0.x;
        Bs[(kb + 1) * SSTRIDE + lrow] = bf0.y;
        Bs[(kb + 2) * SSTRIDE + lrow] = bf0.z;
        Bs[(kb + 3) * SSTRIDE + lrow] = bf0.w;
        Bs[(kb + 4) * SSTRIDE + lrow] = bf1.x;
        Bs[(kb + 5) * SSTRIDE + lrow] = bf1.y;
        Bs[(kb + 6) * SSTRIDE + lrow] = bf1.z;
        Bs[(kb + 7) * SSTRIDE + lrow] = bf1.w;
        __syncthreads();
        if (kt + 1 < NT) {
            const float* an = Aptr + (kt + 1) * BK;
            const float* bn = Bptr + (kt + 1) * BK;
            af0 = *(const float4*)an; af1 = *(const float4*)(an + 4);
            bf0 = *(const float4*)bn; bf1 = *(const float4*)(bn + 4);
        }
#pragma unroll
        for (int k = 0; k < BK; k++) {
            const float* arow = &As[k * SSTRIDE + ty * 8];
            float4 a01 = *(const float4*)(arow);
            float4 a23 = *(const float4*)(arow + 4);
            const float* brow = &Bs[k * SSTRIDE];
            unsigned long long b0 = *(const unsigned long long*)(brow + tx * 2);
            unsigned long long b1 = *(const unsigned long long*)(brow + 32 + tx * 2);
            unsigned long long b2 = *(const unsigned long long*)(brow + 64 + tx * 2);
            unsigned long long b3 = *(const unsigned long long*)(brow + 96 + tx * 2);
            float av[8] = {a01.x, a01.y, a01.z, a01.w, a23.x, a23.y, a23.z, a23.w};
#pragma unroll
            for (int r = 0; r < 8; r++) {
                unsigned long long aa = pack_dup(av[r]);
                ffma2(acc[r][0], aa, b0);
                ffma2(acc[r][1], aa, b1);
                ffma2(acc[r][2], aa, b2);
                ffma2(acc[r][3], aa, b3);
            }
        }
        __syncthreads();
    }

#pragma unroll
    for (int r = 0; r < 8; r++) {
        float* crow = &g_scores[(size_t)(m0 + ty * 8 + r) * YROWS + n0];
#pragma unroll
        for (int g = 0; g < 4; g++) {
            *(unsigned long long*)(crow + g * 32 + tx * 2) = acc[r][g];
        }
    }
}

// ---------------- 3) per-pair Sinkhorn (exp-domain scaling) ----------------
// K = exp2(Z*10*log2e) precomputed once. Iterations are classic Sinkhorn
// scaling: eu = mu / (K ev), ev = nu / (K^T eu) — pure FMA + one rcp each.
// Bounds: |Z2|<=14.43, bin col never masked => exp2 args stay within +-67,
// no overflow/underflow of the dominant terms in fp32.
__global__ __launch_bounds__(64, 12) void sinkhorn_kernel(const float* __restrict__ dbim,
                                                          const float* __restrict__ dblang,
                                                          float* __restrict__ out_match) {
    __shared__ float E[MP1 * LP1];    // exp2(Z2)
    __shared__ float Zs[MP1 * LP1];   // Z2 (for ot score sum)
    __shared__ float eu[MP1];
    __shared__ float ev[LP1];
    __shared__ unsigned char mc[LP1];
    __shared__ float sh_ns;
    __shared__ float wsum[2];

    const int bi = blockIdx.x;
    const int i = bi >> 6;       // image 0..255
    const int j = bi & 63;       // lang  0..63
    const int tid = threadIdx.x; // 64 threads

    if (tid < L_TOK) mc[tid] = g_mask[j * L_TOK + tid];
    if (tid == L_TOK) mc[L_TOK] = 0;
    __syncthreads();
    if (tid == 0) {
        int valid = 0;
        for (int c = 0; c < L_TOK; c++) valid += mc[c] ? 0 : 1;
        sh_ns = (float)valid;
    }

    const float a_im   = fminf(fmaxf(dbim[0],   -1.f), 1.f);
    const float a_lang = fminf(fmaxf(dblang[0], -1.f), 1.f);
    const float SC    = INVREG * LOG2E;   // score -> base-2 scaled
    const float binc2 = a_im   * SC;      // col 32 (all rows incl. corner)
    const float binr2 = a_lang * SC;      // row 49, cols < 32

    // build Z2 and E = exp2(Z2) in smem (masked cols -> NEGV -> E = 0)
    const float* sbase = g_scores + (size_t)i * M_REG * YROWS + (size_t)j * L_TOK;
    {
        int r = tid / LP1, c = tid - r * LP1;
        for (int idx = tid; idx < MP1 * LP1; idx += 64) {
            float val;
            if (c < L_TOK) {
                if (mc[c])          val = NEGV;
                else if (r < M_REG) val = sbase[(size_t)r * YROWS + c] * SC;
                else                val = binr2;
            } else {
                val = binc2;
            }
            Zs[idx] = val;
            E[idx] = ex2f(val);
            r += 1; c += 31;
            if (c >= LP1) { c -= LP1; r += 1; }
        }
    }
    if (tid < LP1) ev[tid] = (tid < L_TOK && mc[tid]) ? 0.f : 1.f;
    __syncthreads();

    // row data register-resident (33 regs, constant across iterations)
    float erow[LP1];
    if (tid < MP1) {
#pragma unroll
        for (int c = 0; c < LP1; c++) erow[c] = E[tid * LP1 + c];
    }
    const bool colActive = (tid < LP1) && !(tid < L_TOK && mc[tid]);

    const float ns = sh_ns;
    const float tot = (float)M_REG + ns;                 // m + ns
    const float mu_v  = (tid < M_REG) ? 1.f : ns;        // * (1/tot)
    const float nu_v  = (tid < L_TOK) ? 1.f : (float)M_REG;
    const float invtot = rcpf(tot);
    const float mu  = mu_v * invtot;
    const float nu  = nu_v * invtot;

    for (int it = 0; it < ITERS; it++) {
        // row pass: eu[r] = mu / sum_c erow[c]*ev[c]
        if (tid < MP1) {
            float s = 0.f;
#pragma unroll
            for (int c = 0; c < LP1; c++) s += erow[c] * ev[c];
            eu[tid] = mu * rcpf(s);
        }
        __syncthreads();
        // col pass: ev[c] = nu / sum_r E[r][c]*eu[r]   (masked cols stay 0)
        if (colActive) {
            float s = 0.f;
#pragma unroll
            for (int r = 0; r < MP1; r++) s += E[r * LP1 + tid] * eu[r];
            ev[tid] = nu * rcpf(s);
        }
        __syncthreads();
    }

    // finalize: Zm = E*eu*ev*(m+ns); matching output + ot partial
    float part = 0.f;
    {
        int r = tid / LP1, c = tid - r * LP1;
        for (int idx = tid; idx < MP1 * LP1; idx += 64) {
            float zm = E[idx] * eu[r] * ev[c] * tot;
            if (out_match) out_match[(size_t)bi * (MP1 * LP1) + idx] = zm;
            if (r < M_REG && c < L_TOK) part += Zs[idx] * zm;  // Zs = score*10*log2e
            r += 1; c += 31;
            if (c >= LP1) { c -= LP1; r += 1; }
        }
    }
#pragma unroll
    for (int o = 16; o; o >>= 1) part += __shfl_down_sync(0xffffffffu, part, o);
    if ((tid & 31) == 0) wsum[tid >> 5] = part;
    __syncthreads();
    // ot = sum(score*zm)/TEMP = part * (REG*LN2) / TEMP = part * LN2
    if (tid == 0) g_ot[bi] = (wsum[0] + wsum[1]) * LN2;
}

// ---------------- 4) InfoNCE loss over ot_scores (256x64) ----------------
__global__ __launch_bounds__(256) void loss_kernel(float* __restrict__ out_loss) {
    __shared__ float sl[8], si[8];
    const int i = threadIdx.x;        // image index 0..255
    const int grp = i >> 2;           // lang of image i
    const float* row = g_ot + i * N_LANG;
    const float pos = row[grp];

    float mx = -INFINITY;
    for (int c = 0; c < N_LANG; c++) mx = fmaxf(mx, row[c]);
    float s = 0.f;
    for (int c = 0; c < N_LANG; c++) s += __expf(row[c] - mx);
    float t_lang = pos - (mx + __logf(s));

    float mx2 = -INFINITY;
    for (int k = 0; k < N_IMG; k++) {
        if (((k >> 2) != grp) || (k == i)) mx2 = fmaxf(mx2, g_ot[k * N_LANG + grp]);
    }
    float s2 = 0.f;
    for (int k = 0; k < N_IMG; k++) {
        if (((k >> 2) != grp) || (k == i)) s2 += __expf(g_ot[k * N_LANG + grp] - mx2);
    }
    float t_im = pos - (mx2 + __logf(s2));

#pragma unroll
    for (int o = 16; o; o >>= 1) {
        t_lang += __shfl_down_sync(0xffffffffu, t_lang, o);
        t_im   += __shfl_down_sync(0xffffffffu, t_im, o);
    }
    if ((i & 31) == 0) { sl[i >> 5] = t_lang; si[i >> 5] = t_im; }
    __syncthreads();
    if (i == 0) {
        float a = 0.f, b = 0.f;
        for (int w = 0; w < 8; w++) { a += sl[w]; b += si[w]; }
        *out_loss = -0.5f * (a + b) / (float)N_IMG;
    }
}

// ---------------- launcher ----------------
extern "C" void kernel_launch(void* const* d_in, const int* in_sizes, int n_in,
                              void* d_out, int out_size) {
    const float* x      = (const float*)d_in[0];
    const float* y      = (const float*)d_in[1];
    const float* dbim   = (const float*)d_in[2];
    const float* dblang = (const float*)d_in[3];
    const void*  ymask  = d_in[4];

    float* outF = (float*)d_out;
    const long long MATCH = (long long)NB * MP1 * LP1;   // 27,033,600
    float* matchPtr = outF;
    float* lossPtr;
    if ((long long)out_size >= MATCH + 1) lossPtr = outF + MATCH;
    else if (out_size == 1)               { lossPtr = outF; matchPtr = nullptr; }
    else                                   lossPtr = outF;  // fallback

    decode_mask_kernel<<<1, 256>>>(ymask);
    {   // normalize
        int rows = XROWS + YROWS;
        int threads = 256;
        int blocks = (rows * 32 + threads - 1) / threads;
        norm_kernel<<<blocks, threads>>>(x, y);
    }
    {   // GEMM: 12544/128 = 98, 2048/128 = 16
        dim3 grid(YROWS / BN, XROWS / BM);
        gemm_kernel<<<grid, 256>>>();
    }
    {   // sinkhorn per (image, lang) pair
        sinkhorn_kernel<<<NB, 64>>>(dbim, dblang, matchPtr);
    }
    {   // loss
        loss_kernel<<<1, 256>>>(lossPtr);
    }
}

// round 14
// speedup vs baseline: 1.7694x; 1.0470x over previous
#include <cuda_runtime.h>
#include <cuda_bf16.h>
#include <math.h>

// ---------------- problem constants ----------------
#define N_LANG   64
#define N_EX     4
#define N_IMG    (N_LANG * N_EX)        // 256
#define M_REG    49
#define L_TOK    32
#define HDIM     512
#define MP1      (M_REG + 1)            // 50
#define LP1      (L_TOK + 1)            // 33
#define NB       (N_IMG * N_LANG)       // 16384 batch items
#define XROWS    (N_IMG * M_REG)        // 12544
#define YROWS    (N_LANG * L_TOK)       // 2048
#define REG      0.1f
#define INVREG   10.0f
#define TEMP     0.1f
#define ITERS    10
#define NEGV     (-1.0e7f)              // sentinel (exp2 -> 0)
#define LOG2E    1.4426950408889634f
#define LN2      0.6931471805599453f

// scratch (static device allocations are the sanctioned workaround)
__device__ float g_xn[(size_t)XROWS * HDIM];      // 25.7 MB
__device__ float g_yn[(size_t)YROWS * HDIM];      //  4.2 MB
__device__ float g_scores[(size_t)XROWS * YROWS]; // 102.8 MB
__device__ float g_ot[NB];
__device__ unsigned char g_mask[YROWS];

__device__ __forceinline__ float ex2f(float x) {
    float r; asm("ex2.approx.ftz.f32 %0, %1;" : "=f"(r) : "f"(x)); return r;
}
__device__ __forceinline__ float rcpf(float x) {
    float r; asm("rcp.approx.ftz.f32 %0, %1;" : "=f"(r) : "f"(x)); return r;
}

// ---------------- 0) decode y_mask regardless of storage dtype ----------------
__global__ void decode_mask_kernel(const void* __restrict__ p) {
    __shared__ int bad;
    if (threadIdx.x == 0) bad = 0;
    __syncthreads();
    const int* ip = (const int*)p;
    for (int k = threadIdx.x; k < 512; k += blockDim.x) {
        int w = ip[k];
        if (w != 0 && w != 1 && w != 0x3f800000) atomicOr(&bad, 1);
    }
    __syncthreads();
    if (bad) {  // byte-encoded mask
        const unsigned char* bp = (const unsigned char*)p;
        for (int k = threadIdx.x; k < YROWS; k += blockDim.x)
            g_mask[k] = bp[k] ? 1 : 0;
    } else {    // 4-byte-encoded mask (int32 0/1 or float32 0.0/1.0)
        for (int k = threadIdx.x; k < YROWS; k += blockDim.x)
            g_mask[k] = ip[k] ? 1 : 0;
    }
}

// ---------------- 1) L2 normalize rows of x and y ----------------
__global__ void norm_kernel(const float* __restrict__ x, const float* __restrict__ y) {
    int row  = (blockIdx.x * blockDim.x + threadIdx.x) >> 5;
    int lane = threadIdx.x & 31;
    if (row >= XROWS + YROWS) return;
    const float* src;
    float* dst;
    if (row < XROWS) { src = x + (size_t)row * HDIM;           dst = g_xn + (size_t)row * HDIM; }
    else             { src = y + (size_t)(row - XROWS) * HDIM; dst = g_yn + (size_t)(row - XROWS) * HDIM; }

    const float4* s4 = (const float4*)src;
    float4 v[4];
    float ss = 0.f;
#pragma unroll
    for (int q = 0; q < 4; q++) {
        v[q] = s4[lane + 32 * q];
        ss += v[q].x * v[q].x + v[q].y * v[q].y + v[q].z * v[q].z + v[q].w * v[q].w;
    }
#pragma unroll
    for (int o = 16; o; o >>= 1) ss += __shfl_xor_sync(0xffffffffu, ss, o);
    float inv = 1.0f / fmaxf(sqrtf(ss), 1e-12f);
    float4* d4 = (float4*)dst;
#pragma unroll
    for (int q = 0; q < 4; q++) {
        float4 w = v[q];
        w.x *= inv; w.y *= inv; w.z *= inv; w.w *= inv;
        d4[lane + 32 * q] = w;
    }
}

// ---------------- 2) scores GEMM: C[12544,2048] = Xn (12544x512) * Yn^T ----
// 128x128x16 tile, 256 threads, 8x8 micro-tile, packed fma.rn.f32x2 (Blackwell).
// (tcgen05 path is unavailable: harness lowers PTX at compute_103, which
//  rejects all tcgen05/TMEM instructions — verified round 12.)
#define BM 128
#define BN 128
#define BK 16
#define SSTRIDE 132   // smem row stride (floats)

__device__ __forceinline__ unsigned long long pack_dup(float x) {
    unsigned long long r;
    asm("mov.b64 %0, {%1, %1};" : "=l"(r) : "f"(x));
    return r;
}
__device__ __forceinline__ void ffma2(unsigned long long& d, unsigned long long a,
                                      unsigned long long b) {
    asm("fma.rn.f32x2 %0, %1, %2, %0;" : "+l"(d) : "l"(a), "l"(b));
}

__global__ __launch_bounds__(256) void gemm_kernel() {
    __shared__ float As[BK * SSTRIDE];
    __shared__ float Bs[BK * SSTRIDE];
    const int tid = threadIdx.x;
    const int m0 = blockIdx.y * BM;
    const int n0 = blockIdx.x * BN;

    const int lrow = tid >> 1;            // 0..127
    const int kb   = (tid & 1) * 8;       // 0 or 8
    const int ty   = tid >> 4;            // 0..15 -> row group
    const int tx   = tid & 15;            // 0..15 -> col pairs

    const float* Aptr = g_xn + (size_t)(m0 + lrow) * HDIM + kb;
    const float* Bptr = g_yn + (size_t)(n0 + lrow) * HDIM + kb;

    unsigned long long acc[8][4];
#pragma unroll
    for (int r = 0; r < 8; r++)
#pragma unroll
        for (int g = 0; g < 4; g++) acc[r][g] = 0ULL;

    float4 af0 = *(const float4*)Aptr;
    float4 af1 = *(const float4*)(Aptr + 4);
    float4 bf0 = *(const float4*)Bptr;
    float4 bf1 = *(const float4*)(Bptr + 4);

    const int NT = HDIM / BK;   // 32 k-tiles
    for (int kt = 0; kt < NT; kt++) {
        As[(kb + 0) * SSTRIDE + lrow] = af0.x;
        As[(kb + 1) * SSTRIDE + lrow] = af0.y;
        As[(kb + 2) * SSTRIDE + lrow] = af0.z;
        As[(kb + 3) * SSTRIDE + lrow] = af0.w;
        As[(kb + 4) * SSTRIDE + lrow] = af1.x;
        As[(kb + 5) * SSTRIDE + lrow] = af1.y;
        As[(kb + 6) * SSTRIDE + lrow] = af1.z;
        As[(kb + 7) * SSTRIDE + lrow] = af1.w;
        Bs[(kb + 0) * SSTRIDE + lrow] = bf0.x;
        Bs[(kb + 1) * SSTRIDE + lrow] = bf0.y;
        Bs[(kb + 2) * SSTRIDE + lrow] = bf0.z;
        Bs[(kb + 3) * SSTRIDE + lrow] = bf0.w;
        Bs[(kb + 4) * SSTRIDE + lrow] = bf1.x;
        Bs[(kb + 5) * SSTRIDE + lrow] = bf1.y;
        Bs[(kb + 6) * SSTRIDE + lrow] = bf1.z;
        Bs[(kb + 7) * SSTRIDE + lrow] = bf1.w;
        __syncthreads();
        if (kt + 1 < NT) {
            const float* an = Aptr + (kt + 1) * BK;
            const float* bn = Bptr + (kt + 1) * BK;
            af0 = *(const float4*)an; af1 = *(const float4*)(an + 4);
            bf0 = *(const float4*)bn; bf1 = *(const float4*)(bn + 4);
        }
#pragma unroll
        for (int k = 0; k < BK; k++) {
            const float* arow = &As[k * SSTRIDE + ty * 8];
            float4 a01 = *(const float4*)(arow);
            float4 a23 = *(const float4*)(arow + 4);
            const float* brow = &Bs[k * SSTRIDE];
            unsigned long long b0 = *(const unsigned long long*)(brow + tx * 2);
            unsigned long long b1 = *(const unsigned long long*)(brow + 32 + tx * 2);
            unsigned long long b2 = *(const unsigned long long*)(brow + 64 + tx * 2);
            unsigned long long b3 = *(const unsigned long long*)(brow + 96 + tx * 2);
            float av[8] = {a01.x, a01.y, a01.z, a01.w, a23.x, a23.y, a23.z, a23.w};
#pragma unroll
            for (int r = 0; r < 8; r++) {
                unsigned long long aa = pack_dup(av[r]);
                ffma2(acc[r][0], aa, b0);
                ffma2(acc[r][1], aa, b1);
                ffma2(acc[r][2], aa, b2);
                ffma2(acc[r][3], aa, b3);
            }
        }
        __syncthreads();
    }

#pragma unroll
    for (int r = 0; r < 8; r++) {
        float* crow = &g_scores[(size_t)(m0 + ty * 8 + r) * YROWS + n0];
#pragma unroll
        for (int g = 0; g < 4; g++) {
            *(unsigned long long*)(crow + g * 32 + tx * 2) = acc[r][g];
        }
    }
}

// ---------------- 3) per-pair Sinkhorn (exp-domain, low-register) ----------
// E = exp2(Z*10*log2e) in smem. Row AND col passes read E from smem
// (bank of E[r*33+c] = (r+c) mod 32 -> <=2-way conflicts). No Zs array:
// finalize recovers the log-score via __log2f(E). Regs ~45 -> occupancy
// roughly doubles vs the erow[33] version (was 36% @ 77 regs).
__global__ __launch_bounds__(64) void sinkhorn_kernel(const float* __restrict__ dbim,
                                                      const float* __restrict__ dblang,
                                                      float* __restrict__ out_match) {
    __shared__ float E[MP1 * LP1];
    __shared__ float eu[MP1];
    __shared__ float ev[LP1];
    __shared__ unsigned char mc[LP1];
    __shared__ float sh_ns;
    __shared__ float wsum[2];

    const int bi = blockIdx.x;
    const int i = bi >> 6;       // image 0..255
    const int j = bi & 63;       // lang  0..63
    const int tid = threadIdx.x; // 64 threads

    if (tid < L_TOK) mc[tid] = g_mask[j * L_TOK + tid];
    if (tid == L_TOK) mc[L_TOK] = 0;
    __syncthreads();
    if (tid == 0) {
        int valid = 0;
        for (int c = 0; c < L_TOK; c++) valid += mc[c] ? 0 : 1;
        sh_ns = (float)valid;
    }

    const float a_im   = fminf(fmaxf(dbim[0],   -1.f), 1.f);
    const float a_lang = fminf(fmaxf(dblang[0], -1.f), 1.f);
    const float SC    = INVREG * LOG2E;   // score -> base-2 scaled
    const float binc2 = a_im   * SC;      // col 32 (all rows incl. corner)
    const float binr2 = a_lang * SC;      // row 49, cols < 32

    // build E = exp2(Z2) in smem (masked cols -> exp2(NEGV) = 0)
    const float* sbase = g_scores + (size_t)i * M_REG * YROWS + (size_t)j * L_TOK;
    {
        int r = tid / LP1, c = tid - r * LP1;
        for (int idx = tid; idx < MP1 * LP1; idx += 64) {
            float val;
            if (c < L_TOK) {
                if (mc[c])          val = NEGV;
                else if (r < M_REG) val = sbase[(size_t)r * YROWS + c] * SC;
                else                val = binr2;
            } else {
                val = binc2;
            }
            E[idx] = ex2f(val);
            r += 1; c += 31;
            if (c >= LP1) { c -= LP1; r += 1; }
        }
    }
    if (tid < LP1) ev[tid] = (tid < L_TOK && mc[tid]) ? 0.f : 1.f;
    __syncthreads();

    const bool colActive = (tid < LP1) && !(tid < L_TOK && mc[tid]);

    const float ns = sh_ns;
    const float tot = (float)M_REG + ns;                 // m + ns
    const float mu_v  = (tid < M_REG) ? 1.f : ns;
    const float nu_v  = (tid < L_TOK) ? 1.f : (float)M_REG;
    const float invtot = rcpf(tot);
    const float mu  = mu_v * invtot;
    const float nu  = nu_v * invtot;

    for (int it = 0; it < ITERS; it++) {
        // row pass: eu[r] = mu / sum_c E[r][c]*ev[c]
        if (tid < MP1) {
            const float* er = &E[tid * LP1];
            float s = 0.f;
#pragma unroll
            for (int c = 0; c < LP1; c++) s += er[c] * ev[c];
            eu[tid] = mu * rcpf(s);
        }
        __syncthreads();
        // col pass: ev[c] = nu / sum_r E[r][c]*eu[r]   (masked cols stay 0)
        if (colActive) {
            float s = 0.f;
#pragma unroll
            for (int r = 0; r < MP1; r++) s += E[r * LP1 + tid] * eu[r];
            ev[tid] = nu * rcpf(s);
        }
        __syncthreads();
    }

    // finalize: Zm = E*eu*ev*(m+ns); match output + ot partial
    // log-score recovered as log2(E) (E >= 2^-14.5 for unmasked entries).
    float part = 0.f;
    {
        int r = tid / LP1, c = tid - r * LP1;
        for (int idx = tid; idx < MP1 * LP1; idx += 64) {
            float e = E[idx];
            float zm = e * eu[r] * ev[c] * tot;
            if (out_match) out_match[(size_t)bi * (MP1 * LP1) + idx] = zm;
            if (r < M_REG && c < L_TOK && zm > 0.f) part += __log2f(e) * zm;
            r += 1; c += 31;
            if (c >= LP1) { c -= LP1; r += 1; }
        }
    }
#pragma unroll
    for (int o = 16; o; o >>= 1) part += __shfl_down_sync(0xffffffffu, part, o);
    if ((tid & 31) == 0) wsum[tid >> 5] = part;
    __syncthreads();
    // ot = sum(score*zm)/TEMP = part * (REG*LN2) / TEMP = part * LN2
    if (tid == 0) g_ot[bi] = (wsum[0] + wsum[1]) * LN2;
}

// ---------------- 4) InfoNCE loss over ot_scores (256x64) ----------------
__global__ __launch_bounds__(256) void loss_kernel(float* __restrict__ out_loss) {
    __shared__ float sl[8], si[8];
    const int i = threadIdx.x;        // image index 0..255
    const int grp = i >> 2;           // lang of image i
    const float* row = g_ot + i * N_LANG;
    const float pos = row[grp];

    float mx = -INFINITY;
    for (int c = 0; c < N_LANG; c++) mx = fmaxf(mx, row[c]);
    float s = 0.f;
    for (int c = 0; c < N_LANG; c++) s += __expf(row[c] - mx);
    float t_lang = pos - (mx + __logf(s));

    float mx2 = -INFINITY;
    for (int k = 0; k < N_IMG; k++) {
        if (((k >> 2) != grp) || (k == i)) mx2 = fmaxf(mx2, g_ot[k * N_LANG + grp]);
    }
    float s2 = 0.f;
    for (int k = 0; k < N_IMG; k++) {
        if (((k >> 2) != grp) || (k == i)) s2 += __expf(g_ot[k * N_LANG + grp] - mx2);
    }
    float t_im = pos - (mx2 + __logf(s2));

#pragma unroll
    for (int o = 16; o; o >>= 1) {
        t_lang += __shfl_down_sync(0xffffffffu, t_lang, o);
        t_im   += __shfl_down_sync(0xffffffffu, t_im, o);
    }
    if ((i & 31) == 0) { sl[i >> 5] = t_lang; si[i >> 5] = t_im; }
    __syncthreads();
    if (i == 0) {
        float a = 0.f, b = 0.f;
        for (int w = 0; w < 8; w++) { a += sl[w]; b += si[w]; }
        *out_loss = -0.5f * (a + b) / (float)N_IMG;
    }
}

// ---------------- launcher ----------------
extern "C" void kernel_launch(void* const* d_in, const int* in_sizes, int n_in,
                              void* d_out, int out_size) {
    const float* x      = (const float*)d_in[0];
    const float* y      = (const float*)d_in[1];
    const float* dbim   = (const float*)d_in[2];
    const float* dblang = (const float*)d_in[3];
    const void*  ymask  = d_in[4];

    float* outF = (float*)d_out;
    const long long MATCH = (long long)NB * MP1 * LP1;   // 27,033,600
    float* matchPtr = outF;
    float* lossPtr;
    if ((long long)out_size >= MATCH + 1) lossPtr = outF + MATCH;
    else if (out_size == 1)               { lossPtr = outF; matchPtr = nullptr; }
    else                                   lossPtr = outF;

    decode_mask_kernel<<<1, 256>>>(ymask);
    {   // normalize
        int rows = XROWS + YROWS;
        int blocks = (rows * 32 + 255) / 256;
        norm_kernel<<<blocks, 256>>>(x, y);
    }
    {   // GEMM: 12544/128 = 98, 2048/128 = 16
        dim3 grid(YROWS / BN, XROWS / BM);
        gemm_kernel<<<grid, 256>>>();
    }
    sinkhorn_kernel<<<NB, 64>>>(dbim, dblang, matchPtr);
    loss_kernel<<<1, 256>>>(lossPtr);
}